// round 10
// baseline (speedup 1.0000x reference)
#include <cuda_runtime.h>

#define PI_F 3.14159265358979f

typedef unsigned long long u64;
struct P { u64 v; };

__device__ __forceinline__ P mkP(u64 x){ P r; r.v = x; return r; }
__device__ __forceinline__ P pack2(float lo, float hi){
    P r; asm("mov.b64 %0,{%1,%2};" : "=l"(r.v) : "f"(lo), "f"(hi)); return r;
}
__device__ __forceinline__ P dupP(float v){
    P r; asm("mov.b64 %0,{%1,%1};" : "=l"(r.v) : "f"(v)); return r;
}
__device__ __forceinline__ void unpack2(P a, float& lo, float& hi){
    asm("mov.b64 {%0,%1},%2;" : "=f"(lo), "=f"(hi) : "l"(a.v));
}
__device__ __forceinline__ P fma2(P a, P b, P c){
    P r; asm("fma.rn.f32x2 %0,%1,%2,%3;" : "=l"(r.v) : "l"(a.v), "l"(b.v), "l"(c.v)); return r;
}
#define K_ZERO (mkP(0ULL))
__device__ __forceinline__ P mul2(P a, P b){ return fma2(a, b, K_ZERO); }

// shared layout (floats). MLP weights TRANSPOSED, adjacent-neuron pairs.
#define OFF_W1   0      // 64
#define OFF_B1   64     // 16
#define OFF_W2   80     // 512
#define OFF_B2   592    // 32
#define OFF_W3   624    // 512
#define OFF_B3   1136   // 16
#define OFF_C    1152   // 60 (30 pair-duplicated Heisenberg coefficients)
#define SW_TOTAL 1216

#define BLK 192

__global__ __launch_bounds__(BLK, 3) void hqae_kernel(
    const float* __restrict__ x,  const float* __restrict__ qw,
    const float* __restrict__ W1, const float* __restrict__ b1,
    const float* __restrict__ W2, const float* __restrict__ b2,
    const float* __restrict__ W3, const float* __restrict__ b3,
    float* __restrict__ out, int n)
{
    __shared__ __align__(16) float sw[SW_TOTAL];
    const int tid = threadIdx.x;

    for (int i = tid; i < 64;  i += BLK){ int k = i >> 4, j = i & 15; sw[OFF_W1 + i] = W1[j*4 + k]; }
    for (int i = tid; i < 512; i += BLK){ int k = i >> 5, j = i & 31; sw[OFF_W2 + i] = W2[j*16 + k]; }
    for (int i = tid; i < 512; i += BLK){ int k = i >> 4, j = i & 15; sw[OFF_W3 + i] = W3[j*32 + k]; }
    for (int i = tid; i < 16;  i += BLK) sw[OFF_B1 + i] = b1[i];
    for (int i = tid; i < 32;  i += BLK) sw[OFF_B2 + i] = b2[i];
    for (int i = tid; i < 16;  i += BLK) sw[OFF_B3 + i] = b3[i];
    if (tid == 0) {
        // Heisenberg coefficients: Z_i conjugated back through CNOT2 / RY(var) / CNOT1.
        // (Variational RZ is diagonal unit-phase -> vanishes under |.|^2.)
        float c[4], s[4];
#pragma unroll
        for (int i = 0; i < 4; i++) __sincosf(qw[2*i], &s[i], &c[i]);  // FULL angle (Bloch rotation)
        float K[30];
        K[0]=+c[0];                 K[1]=-s[0];
        K[2]=+c[0]*c[1];            K[3]=-c[0]*s[1];
        K[4]=+s[0]*c[1];            K[5]=+s[0]*s[1];
        K[6]=+c[0]*c[1]*c[2];       K[7]=-c[0]*c[1]*s[2];
        K[8]=+c[0]*s[1]*c[2];       K[9]=+c[0]*s[1]*s[2];
        K[10]=-s[0]*c[1]*c[2];      K[11]=-s[0]*c[1]*s[2];
        K[12]=-s[0]*s[1]*c[2];      K[13]=-s[0]*s[1]*s[2];
        K[14]=+c[0]*c[1]*c[2]*c[3]; K[15]=-c[0]*c[1]*c[2]*s[3];
        K[16]=+c[0]*c[1]*s[2]*c[3]; K[17]=+c[0]*c[1]*s[2]*s[3];
        K[18]=-c[0]*s[1]*c[2]*c[3]; K[19]=-c[0]*s[1]*c[2]*s[3];
        K[20]=-c[0]*s[1]*s[2]*c[3]; K[21]=-c[0]*s[1]*s[2]*s[3];
        K[22]=+s[0]*c[1]*c[2]*c[3]; K[23]=+s[0]*c[1]*c[2]*s[3];
        K[24]=-s[0]*c[1]*s[2]*c[3]; K[25]=+s[0]*c[1]*s[2]*s[3];
        K[26]=+s[0]*s[1]*c[2]*c[3]; K[27]=+s[0]*s[1]*c[2]*s[3];
        K[28]=+s[0]*s[1]*s[2]*c[3]; K[29]=+s[0]*s[1]*s[2]*s[3];
#pragma unroll
        for (int i = 0; i < 30; i++){ sw[OFF_C + 2*i] = K[i]; sw[OFF_C + 2*i + 1] = K[i]; }
    }
    __syncthreads();

    const int half = n >> 1;                   // pair (b, b+half)
    const int b0 = blockIdx.x * BLK + tid;
    if (b0 >= half) return;
    const int b1i = b0 + half;

    // ---- load x rows for both elements ----
    const float4* xv0 = (const float4*)(x + (size_t)b0  * 16);
    const float4* xv1 = (const float4*)(x + (size_t)b1i * 16);
    float4 q0 = xv0[0], q1 = xv0[1];
    float4 r0 = xv1[0], r1 = xv1[1];
    float xA[8] = {q0.x, q0.y, q0.z, q0.w, q1.x, q1.y, q1.z, q1.w};
    float xB[8] = {r0.x, r0.y, r0.z, r0.w, r1.x, r1.y, r1.z, r1.w};

    // ---- Bloch vectors of the input product state (batch-pair packed) ----
    P bz[4], bx[4], by[4];
#pragma unroll
    for (int i = 0; i < 4; i++) {
        float sA, cA, sB, cB, pA, qA, pB, qB;
        __sincosf(xA[i] * PI_F, &sA, &cA);
        __sincosf(xB[i] * PI_F, &sB, &cB);
        __sincosf(xA[i+4] * PI_F, &pA, &qA);
        __sincosf(xB[i+4] * PI_F, &pB, &qB);
        bz[i] = pack2(cA, cB);
        P sp = pack2(sA, sB);
        bx[i] = mul2(sp, pack2(qA, qB));
        by[i] = mul2(sp, pack2(pA, pB));
    }

    // ---- 30-term Pauli-string evaluation ----
    const P* Kp = (const P*)(sw + OFF_C);

    P a_ = mul2(bx[0], bx[1]);   // x0x1
    P b_ = mul2(bx[1], bx[2]);   // x1x2
    P c_ = mul2(bx[0], bx[2]);   // x0x2
    P d_ = mul2(by[0], by[1]);   // y0y1
    P e_ = mul2(by[1], by[2]);   // y1y2
    P f_ = mul2(bx[2], bx[3]);   // x2x3
    P h_ = mul2(bx[0], bx[3]);   // x0x3
    P i_ = mul2(bz[0], bz[2]);   // z0z2
    P j_ = mul2(by[2], by[3]);   // y2y3
    P k_ = mul2(bz[1], bz[3]);   // z1z3
    P l_ = mul2(bz[0], bx[1]);   // z0x1
    P m_ = mul2(by[0], bz[1]);   // y0z1
    P u_ = mul2(bz[0], b_);      // z0x1x2
    P v_ = mul2(a_, bz[2]);      // x0x1z2
    P w_ = mul2(m_, by[2]);      // y0z1y2

    P e0 = fma2(Kp[1], a_, mul2(Kp[0], bz[0]));

    P e1 = fma2(Kp[3], u_, mul2(Kp[2], bz[1]));
    e1 = fma2(Kp[4], d_, e1);
    e1 = fma2(Kp[5], c_, e1);

    P e2 = mul2(Kp[6], i_);
    e2 = fma2(Kp[7],  mul2(bz[1], f_), e2);
    e2 = fma2(Kp[8],  e_, e2);
    e2 = fma2(Kp[9],  mul2(l_, bx[3]), e2);
    e2 = fma2(Kp[10], v_, e2);
    e2 = fma2(Kp[11], mul2(d_, f_), e2);
    e2 = fma2(Kp[12], w_, e2);
    e2 = fma2(Kp[13], h_, e2);

    P e3 = mul2(Kp[14], k_);
    e3 = fma2(Kp[15], mul2(i_, bx[3]), e3);
    e3 = fma2(Kp[16], mul2(bz[0], j_), e3);
    e3 = fma2(Kp[17], mul2(bz[1], bx[2]), e3);
    e3 = fma2(Kp[18], mul2(u_, bz[3]), e3);
    e3 = fma2(Kp[19], mul2(e_, bx[3]), e3);
    e3 = fma2(Kp[20], mul2(mul2(by[1], bz[2]), by[3]), e3);
    e3 = fma2(Kp[21], l_, e3);
    e3 = fma2(Kp[22], mul2(d_, bz[3]), e3);
    e3 = fma2(Kp[23], mul2(v_, bx[3]), e3);
    e3 = fma2(Kp[24], mul2(a_, j_), e3);
    e3 = fma2(Kp[25], mul2(d_, bx[2]), e3);
    e3 = fma2(Kp[26], mul2(c_, bz[3]), e3);
    e3 = fma2(Kp[27], mul2(w_, bx[3]), e3);
    e3 = fma2(Kp[28], mul2(mul2(m_, bz[2]), by[3]), e3);
    e3 = fma2(Kp[29], bx[0], e3);

    float zA[4], zB[4];
    unpack2(e0, zA[0], zB[0]);
    unpack2(e1, zA[1], zB[1]);
    unpack2(e2, zA[2], zB[2]);
    unpack2(e3, zA[3], zB[3]);

    // ================= MLP: neuron-pair packing; chunking minimized (112-reg budget) ====
    const P* B1p = (const P*)(sw + OFF_B1);
    const P* B2p = (const P*)(sw + OFF_B2);
    const P* B3p = (const P*)(sw + OFF_B3);

    // ---- layer 1: 4 -> 16 (full width) ----
    float h1A[16], h1B[16];
    {
        P aA[8], aB[8];
#pragma unroll
        for (int jp = 0; jp < 8; jp++) { P bb = B1p[jp]; aA[jp] = bb; aB[jp] = bb; }
#pragma unroll
        for (int k = 0; k < 4; k++) {
            P dA = dupP(zA[k]), dB = dupP(zB[k]);
            const ulonglong2* row = (const ulonglong2*)(sw + OFF_W1 + k*16);
#pragma unroll
            for (int q = 0; q < 4; q++) {
                ulonglong2 u = row[q];
                P w0 = mkP(u.x), w1 = mkP(u.y);
                aA[2*q]   = fma2(w0, dA, aA[2*q]);
                aA[2*q+1] = fma2(w1, dA, aA[2*q+1]);
                aB[2*q]   = fma2(w0, dB, aB[2*q]);
                aB[2*q+1] = fma2(w1, dB, aB[2*q+1]);
            }
        }
#pragma unroll
        for (int jp = 0; jp < 8; jp++) {
            float lo, hi;
            unpack2(aA[jp], lo, hi);
            h1A[2*jp] = fmaxf(lo, 0.0f); h1A[2*jp+1] = fmaxf(hi, 0.0f);
            unpack2(aB[jp], lo, hi);
            h1B[2*jp] = fmaxf(lo, 0.0f); h1B[2*jp+1] = fmaxf(hi, 0.0f);
        }
    }

    // ---- layer 2: 16 -> 32, 2 chunks of 16 neurons (accs 8P per elem) ----
    float h2A[32], h2B[32];
#pragma unroll
    for (int c = 0; c < 2; c++) {
        P aA[8], aB[8];
#pragma unroll
        for (int jp = 0; jp < 8; jp++) { P bb = B2p[c*8 + jp]; aA[jp] = bb; aB[jp] = bb; }
#pragma unroll
        for (int k = 0; k < 16; k++) {
            P dA = dupP(h1A[k]), dB = dupP(h1B[k]);
            const ulonglong2* row = (const ulonglong2*)(sw + OFF_W2 + k*32 + c*16);
#pragma unroll
            for (int q = 0; q < 4; q++) {
                ulonglong2 u = row[q];
                P w0 = mkP(u.x), w1 = mkP(u.y);
                aA[2*q]   = fma2(w0, dA, aA[2*q]);
                aA[2*q+1] = fma2(w1, dA, aA[2*q+1]);
                aB[2*q]   = fma2(w0, dB, aB[2*q]);
                aB[2*q+1] = fma2(w1, dB, aB[2*q+1]);
            }
        }
#pragma unroll
        for (int jp = 0; jp < 8; jp++) {
            float lo, hi;
            unpack2(aA[jp], lo, hi);
            h2A[c*16 + 2*jp] = fmaxf(lo, 0.0f); h2A[c*16 + 2*jp+1] = fmaxf(hi, 0.0f);
            unpack2(aB[jp], lo, hi);
            h2B[c*16 + 2*jp] = fmaxf(lo, 0.0f); h2B[c*16 + 2*jp+1] = fmaxf(hi, 0.0f);
        }
    }

    // ---- layer 3: 32 -> 16, single chunk (dups hoisted per k) ----
    float* o0 = out + (size_t)b0  * 16;
    float* o1 = out + (size_t)b1i * 16;
    {
        P aA[8], aB[8];
#pragma unroll
        for (int jp = 0; jp < 8; jp++) { P bb = B3p[jp]; aA[jp] = bb; aB[jp] = bb; }
#pragma unroll
        for (int k = 0; k < 32; k++) {
            P dA = dupP(h2A[k]), dB = dupP(h2B[k]);
            const ulonglong2* row = (const ulonglong2*)(sw + OFF_W3 + k*16);
#pragma unroll
            for (int q = 0; q < 4; q++) {
                ulonglong2 u = row[q];
                P w0 = mkP(u.x), w1 = mkP(u.y);
                aA[2*q]   = fma2(w0, dA, aA[2*q]);
                aA[2*q+1] = fma2(w1, dA, aA[2*q+1]);
                aB[2*q]   = fma2(w0, dB, aB[2*q]);
                aB[2*q+1] = fma2(w1, dB, aB[2*q+1]);
            }
        }
#pragma unroll
        for (int g = 0; g < 4; g++) {
            float4 v;
            unpack2(aA[2*g],   v.x, v.y);
            unpack2(aA[2*g+1], v.z, v.w);
            ((float4*)o0)[g] = v;
            unpack2(aB[2*g],   v.x, v.y);
            unpack2(aB[2*g+1], v.z, v.w);
            ((float4*)o1)[g] = v;
        }
    }
}

extern "C" void kernel_launch(void* const* d_in, const int* in_sizes, int n_in,
                              void* d_out, int out_size)
{
    const float* x  = (const float*)d_in[0];
    const float* qw = (const float*)d_in[1];
    const float* W1 = (const float*)d_in[2];
    const float* b1 = (const float*)d_in[3];
    const float* W2 = (const float*)d_in[4];
    const float* b2 = (const float*)d_in[5];
    const float* W3 = (const float*)d_in[6];
    const float* b3 = (const float*)d_in[7];
    float* out = (float*)d_out;

    const int n = in_sizes[0] / 16;           // B (even)
    const int half = n >> 1;
    const int blocks = (half + BLK - 1) / BLK;
    hqae_kernel<<<blocks, BLK>>>(x, qw, W1, b1, W2, b2, W3, b3, out, n);
}

// round 11
// speedup vs baseline: 1.0640x; 1.0640x over previous
#include <cuda_runtime.h>

#define PI_F 3.14159265358979f

typedef unsigned long long u64;
struct P { u64 v; };

__device__ __forceinline__ P mkP(u64 x){ P r; r.v = x; return r; }
__device__ __forceinline__ P pack2(float lo, float hi){
    P r; asm("mov.b64 %0,{%1,%2};" : "=l"(r.v) : "f"(lo), "f"(hi)); return r;
}
__device__ __forceinline__ P dupP(float v){
    P r; asm("mov.b64 %0,{%1,%1};" : "=l"(r.v) : "f"(v)); return r;
}
__device__ __forceinline__ void unpack2(P a, float& lo, float& hi){
    asm("mov.b64 {%0,%1},%2;" : "=f"(lo), "=f"(hi) : "l"(a.v));
}
__device__ __forceinline__ P fma2(P a, P b, P c){
    P r; asm("fma.rn.f32x2 %0,%1,%2,%3;" : "=l"(r.v) : "l"(a.v), "l"(b.v), "l"(c.v)); return r;
}
#define K_ZERO (mkP(0ULL))
__device__ __forceinline__ P mul2(P a, P b){ return fma2(a, b, K_ZERO); }

// shared layout (floats). MLP weights TRANSPOSED, adjacent-neuron pairs.
#define OFF_W1   0      // 64
#define OFF_B1   64     // 16
#define OFF_W2   80     // 512
#define OFF_B2   592    // 32
#define OFF_W3   624    // 512
#define OFF_B3   1136   // 16
#define OFF_C    1152   // 60 (30 pair-duplicated Heisenberg coefficients)
#define SW_TOTAL 1216

#define BLK 128

// Quantum encoder for one packed batch-pair: xA/xB are the two 16-feature rows,
// writes 4 packed PauliZ expvals (lane0=A, lane1=B).
__device__ __forceinline__ void quantum_pair(
    const float* __restrict__ xA, const float* __restrict__ xB,
    const float* __restrict__ sw, P* __restrict__ eo)
{
    P bz[4], bx[4], by[4];
#pragma unroll
    for (int i = 0; i < 4; i++) {
        float sA, cA, sB, cB, pA, qA, pB, qB;
        __sincosf(xA[i] * PI_F, &sA, &cA);
        __sincosf(xB[i] * PI_F, &sB, &cB);
        __sincosf(xA[i+4] * PI_F, &pA, &qA);
        __sincosf(xB[i+4] * PI_F, &pB, &qB);
        bz[i] = pack2(cA, cB);
        P sp = pack2(sA, sB);
        bx[i] = mul2(sp, pack2(qA, qB));
        by[i] = mul2(sp, pack2(pA, pB));
    }
    const P* Kp = (const P*)(sw + OFF_C);

    P a_ = mul2(bx[0], bx[1]);
    P b_ = mul2(bx[1], bx[2]);
    P c_ = mul2(bx[0], bx[2]);
    P d_ = mul2(by[0], by[1]);
    P e_ = mul2(by[1], by[2]);
    P f_ = mul2(bx[2], bx[3]);
    P h_ = mul2(bx[0], bx[3]);
    P i_ = mul2(bz[0], bz[2]);
    P j_ = mul2(by[2], by[3]);
    P k_ = mul2(bz[1], bz[3]);
    P l_ = mul2(bz[0], bx[1]);
    P m_ = mul2(by[0], bz[1]);
    P u_ = mul2(bz[0], b_);
    P v_ = mul2(a_, bz[2]);
    P w_ = mul2(m_, by[2]);

    eo[0] = fma2(Kp[1], a_, mul2(Kp[0], bz[0]));

    P e1 = fma2(Kp[3], u_, mul2(Kp[2], bz[1]));
    e1 = fma2(Kp[4], d_, e1);
    eo[1] = fma2(Kp[5], c_, e1);

    P e2 = mul2(Kp[6], i_);
    e2 = fma2(Kp[7],  mul2(bz[1], f_), e2);
    e2 = fma2(Kp[8],  e_, e2);
    e2 = fma2(Kp[9],  mul2(l_, bx[3]), e2);
    e2 = fma2(Kp[10], v_, e2);
    e2 = fma2(Kp[11], mul2(d_, f_), e2);
    e2 = fma2(Kp[12], w_, e2);
    eo[2] = fma2(Kp[13], h_, e2);

    P e3 = mul2(Kp[14], k_);
    e3 = fma2(Kp[15], mul2(i_, bx[3]), e3);
    e3 = fma2(Kp[16], mul2(bz[0], j_), e3);
    e3 = fma2(Kp[17], mul2(bz[1], bx[2]), e3);
    e3 = fma2(Kp[18], mul2(u_, bz[3]), e3);
    e3 = fma2(Kp[19], mul2(e_, bx[3]), e3);
    e3 = fma2(Kp[20], mul2(mul2(by[1], bz[2]), by[3]), e3);
    e3 = fma2(Kp[21], l_, e3);
    e3 = fma2(Kp[22], mul2(d_, bz[3]), e3);
    e3 = fma2(Kp[23], mul2(v_, bx[3]), e3);
    e3 = fma2(Kp[24], mul2(a_, j_), e3);
    e3 = fma2(Kp[25], mul2(d_, bx[2]), e3);
    e3 = fma2(Kp[26], mul2(c_, bz[3]), e3);
    e3 = fma2(Kp[27], mul2(w_, bx[3]), e3);
    e3 = fma2(Kp[28], mul2(mul2(m_, bz[2]), by[3]), e3);
    eo[3] = fma2(Kp[29], bx[0], e3);
}

__global__ __launch_bounds__(BLK, 2) void hqae_kernel(
    const float* __restrict__ x,  const float* __restrict__ qw,
    const float* __restrict__ W1, const float* __restrict__ b1,
    const float* __restrict__ W2, const float* __restrict__ b2,
    const float* __restrict__ W3, const float* __restrict__ b3,
    float* __restrict__ out, int n)
{
    __shared__ __align__(16) float sw[SW_TOTAL];
    const int tid = threadIdx.x;

    for (int i = tid; i < 64;  i += BLK){ int k = i >> 4, j = i & 15; sw[OFF_W1 + i] = W1[j*4 + k]; }
    for (int i = tid; i < 512; i += BLK){ int k = i >> 5, j = i & 31; sw[OFF_W2 + i] = W2[j*16 + k]; }
    for (int i = tid; i < 512; i += BLK){ int k = i >> 4, j = i & 15; sw[OFF_W3 + i] = W3[j*32 + k]; }
    for (int i = tid; i < 16;  i += BLK) sw[OFF_B1 + i] = b1[i];
    for (int i = tid; i < 32;  i += BLK) sw[OFF_B2 + i] = b2[i];
    for (int i = tid; i < 16;  i += BLK) sw[OFF_B3 + i] = b3[i];
    if (tid == 0) {
        // Heisenberg coefficients (variational RZ drops under |.|^2).
        float c[4], s[4];
#pragma unroll
        for (int i = 0; i < 4; i++) __sincosf(qw[2*i], &s[i], &c[i]);
        float K[30];
        K[0]=+c[0];                 K[1]=-s[0];
        K[2]=+c[0]*c[1];            K[3]=-c[0]*s[1];
        K[4]=+s[0]*c[1];            K[5]=+s[0]*s[1];
        K[6]=+c[0]*c[1]*c[2];       K[7]=-c[0]*c[1]*s[2];
        K[8]=+c[0]*s[1]*c[2];       K[9]=+c[0]*s[1]*s[2];
        K[10]=-s[0]*c[1]*c[2];      K[11]=-s[0]*c[1]*s[2];
        K[12]=-s[0]*s[1]*c[2];      K[13]=-s[0]*s[1]*s[2];
        K[14]=+c[0]*c[1]*c[2]*c[3]; K[15]=-c[0]*c[1]*c[2]*s[3];
        K[16]=+c[0]*c[1]*s[2]*c[3]; K[17]=+c[0]*c[1]*s[2]*s[3];
        K[18]=-c[0]*s[1]*c[2]*c[3]; K[19]=-c[0]*s[1]*c[2]*s[3];
        K[20]=-c[0]*s[1]*s[2]*c[3]; K[21]=-c[0]*s[1]*s[2]*s[3];
        K[22]=+s[0]*c[1]*c[2]*c[3]; K[23]=+s[0]*c[1]*c[2]*s[3];
        K[24]=-s[0]*c[1]*s[2]*c[3]; K[25]=+s[0]*c[1]*s[2]*s[3];
        K[26]=+s[0]*s[1]*c[2]*c[3]; K[27]=+s[0]*s[1]*c[2]*s[3];
        K[28]=+s[0]*s[1]*s[2]*c[3]; K[29]=+s[0]*s[1]*s[2]*s[3];
#pragma unroll
        for (int i = 0; i < 30; i++){ sw[OFF_C + 2*i] = K[i]; sw[OFF_C + 2*i + 1] = K[i]; }
    }
    __syncthreads();

    const int quart = n >> 2;                 // elements b0, +q, +2q, +3q
    const int b0 = blockIdx.x * BLK + tid;
    if (b0 >= quart) return;

    // ---- load x rows for 4 elements ----
    float xr[4][8];
#pragma unroll
    for (int e = 0; e < 4; e++) {
        const float4* xv = (const float4*)(x + (size_t)(b0 + e*quart) * 16);
        float4 v0 = xv[0], v1 = xv[1];
        xr[e][0]=v0.x; xr[e][1]=v0.y; xr[e][2]=v0.z; xr[e][3]=v0.w;
        xr[e][4]=v1.x; xr[e][5]=v1.y; xr[e][6]=v1.z; xr[e][7]=v1.w;
    }

    // ---- quantum encoder: two packed pairs (0,1) and (2,3) ----
    float z[4][4];
    {
        P ep[4];
        quantum_pair(xr[0], xr[1], sw, ep);
#pragma unroll
        for (int i = 0; i < 4; i++) unpack2(ep[i], z[0][i], z[1][i]);
        quantum_pair(xr[2], xr[3], sw, ep);
#pragma unroll
        for (int i = 0; i < 4; i++) unpack2(ep[i], z[2][i], z[3][i]);
    }

    // ================= MLP: neuron-pair packing, weights shared by 4 elements ==========
    const P* B1p = (const P*)(sw + OFF_B1);
    const P* B2p = (const P*)(sw + OFF_B2);
    const P* B3p = (const P*)(sw + OFF_B3);

    // ---- layer 1: 4 -> 16 ----
    float h1[4][16];
    {
        P acc[4][8];
#pragma unroll
        for (int jp = 0; jp < 8; jp++) {
            P bb = B1p[jp];
#pragma unroll
            for (int e = 0; e < 4; e++) acc[e][jp] = bb;
        }
#pragma unroll
        for (int k = 0; k < 4; k++) {
            P d[4];
#pragma unroll
            for (int e = 0; e < 4; e++) d[e] = dupP(z[e][k]);
            const ulonglong2* row = (const ulonglong2*)(sw + OFF_W1 + k*16);
#pragma unroll
            for (int q = 0; q < 4; q++) {
                ulonglong2 u = row[q];
                P w0 = mkP(u.x), w1 = mkP(u.y);
#pragma unroll
                for (int e = 0; e < 4; e++) {
                    acc[e][2*q]   = fma2(w0, d[e], acc[e][2*q]);
                    acc[e][2*q+1] = fma2(w1, d[e], acc[e][2*q+1]);
                }
            }
        }
#pragma unroll
        for (int e = 0; e < 4; e++)
#pragma unroll
            for (int jp = 0; jp < 8; jp++) {
                float lo, hi;
                unpack2(acc[e][jp], lo, hi);
                h1[e][2*jp] = fmaxf(lo, 0.0f); h1[e][2*jp+1] = fmaxf(hi, 0.0f);
            }
    }

    // ---- layer 2: 16 -> 32, 2 chunks of 16 neurons ----
    float h2[4][32];
#pragma unroll
    for (int c = 0; c < 2; c++) {
        P acc[4][8];
#pragma unroll
        for (int jp = 0; jp < 8; jp++) {
            P bb = B2p[c*8 + jp];
#pragma unroll
            for (int e = 0; e < 4; e++) acc[e][jp] = bb;
        }
#pragma unroll
        for (int k = 0; k < 16; k++) {
            P d[4];
#pragma unroll
            for (int e = 0; e < 4; e++) d[e] = dupP(h1[e][k]);
            const ulonglong2* row = (const ulonglong2*)(sw + OFF_W2 + k*32 + c*16);
#pragma unroll
            for (int q = 0; q < 4; q++) {
                ulonglong2 u = row[q];
                P w0 = mkP(u.x), w1 = mkP(u.y);
#pragma unroll
                for (int e = 0; e < 4; e++) {
                    acc[e][2*q]   = fma2(w0, d[e], acc[e][2*q]);
                    acc[e][2*q+1] = fma2(w1, d[e], acc[e][2*q+1]);
                }
            }
        }
#pragma unroll
        for (int e = 0; e < 4; e++)
#pragma unroll
            for (int jp = 0; jp < 8; jp++) {
                float lo, hi;
                unpack2(acc[e][jp], lo, hi);
                h2[e][c*16 + 2*jp] = fmaxf(lo, 0.0f); h2[e][c*16 + 2*jp+1] = fmaxf(hi, 0.0f);
            }
    }

    // ---- layer 3: 32 -> 16, full width, all 4 elements ----
    {
        P acc[4][8];
#pragma unroll
        for (int jp = 0; jp < 8; jp++) {
            P bb = B3p[jp];
#pragma unroll
            for (int e = 0; e < 4; e++) acc[e][jp] = bb;
        }
#pragma unroll
        for (int k = 0; k < 32; k++) {
            P d[4];
#pragma unroll
            for (int e = 0; e < 4; e++) d[e] = dupP(h2[e][k]);
            const ulonglong2* row = (const ulonglong2*)(sw + OFF_W3 + k*16);
#pragma unroll
            for (int q = 0; q < 4; q++) {
                ulonglong2 u = row[q];
                P w0 = mkP(u.x), w1 = mkP(u.y);
#pragma unroll
                for (int e = 0; e < 4; e++) {
                    acc[e][2*q]   = fma2(w0, d[e], acc[e][2*q]);
                    acc[e][2*q+1] = fma2(w1, d[e], acc[e][2*q+1]);
                }
            }
        }
#pragma unroll
        for (int e = 0; e < 4; e++) {
            float* o = out + (size_t)(b0 + e*quart) * 16;
#pragma unroll
            for (int g = 0; g < 4; g++) {
                float4 v;
                unpack2(acc[e][2*g],   v.x, v.y);
                unpack2(acc[e][2*g+1], v.z, v.w);
                ((float4*)o)[g] = v;
            }
        }
    }
}

extern "C" void kernel_launch(void* const* d_in, const int* in_sizes, int n_in,
                              void* d_out, int out_size)
{
    const float* x  = (const float*)d_in[0];
    const float* qw = (const float*)d_in[1];
    const float* W1 = (const float*)d_in[2];
    const float* b1 = (const float*)d_in[3];
    const float* W2 = (const float*)d_in[4];
    const float* b2 = (const float*)d_in[5];
    const float* W3 = (const float*)d_in[6];
    const float* b3 = (const float*)d_in[7];
    float* out = (float*)d_out;

    const int n = in_sizes[0] / 16;           // B (divisible by 4)
    const int quart = n >> 2;
    const int blocks = (quart + BLK - 1) / BLK;
    hqae_kernel<<<blocks, BLK>>>(x, qw, W1, b1, W2, b2, W3, b3, out, n);
}